// round 1
// baseline (speedup 1.0000x reference)
#include <cuda_runtime.h>
#include <cstdint>

#define BATCH 2
#define TT 512
#define DM 768
#define DI 1536
#define DS 16
#define NROW (BATCH*TT)          // 1024
#define KCONV 4
#define KW (KCONV*DI)            // 6144

// ---------------- scratch (device globals; no allocation allowed) ----------------
__device__ __align__(16) float g_xn   [NROW*DM];
__device__ __align__(16) float g_xz   [NROW*2*DI];
__device__ __align__(16) float g_xpad [BATCH*(TT+3)*DI];
__device__ __align__(16) float g_xact [NROW*DI];
__device__ __align__(16) float g_wc   [DI*KW];
__device__ __align__(16) float g_xssm [NROW*33];
__device__ __align__(16) float g_decay[NROW*DI];
__device__ __align__(16) float g_hist [(size_t)BATCH*TT*DS*DI];   // [b][s][n][d]
__device__ __align__(16) float g_G    [NROW*DI];
__device__ __align__(16) int   g_nz   [NROW*TT];
__device__ int   g_nnz[NROW];
__device__ float g_invdeg[NROW];

__device__ __forceinline__ float siluf(float v){ return v / (1.f + __expf(-v)); }

// ---------------- layernorm ----------------
__global__ void ln_kernel(const float* __restrict__ x,
                          const float* __restrict__ sc,
                          const float* __restrict__ bi,
                          float* __restrict__ out)
{
    int m = blockIdx.x;
    const float* xr = x + (size_t)m*DM;
    int tid = threadIdx.x;
    float v[3]; float s=0.f, sq=0.f;
#pragma unroll
    for (int q=0;q<3;q++){ v[q]=xr[tid+q*256]; s+=v[q]; sq+=v[q]*v[q]; }
#pragma unroll
    for (int o=16;o;o>>=1){ s+=__shfl_down_sync(~0u,s,o); sq+=__shfl_down_sync(~0u,sq,o); }
    __shared__ float sh0[8], sh1[8];
    int lane=tid&31, w=tid>>5;
    if (lane==0){ sh0[w]=s; sh1[w]=sq; }
    __syncthreads();
    __shared__ float smu, srs;
    if (tid==0){
        float S=0.f,SQ=0.f;
#pragma unroll
        for (int i=0;i<8;i++){ S+=sh0[i]; SQ+=sh1[i]; }
        float mu=S/(float)DM;
        float var=SQ/(float)DM - mu*mu;
        smu=mu; srs=rsqrtf(var+1e-5f);
    }
    __syncthreads();
    float mu=smu, rs=srs;
#pragma unroll
    for (int q=0;q<3;q++){
        int k=tid+q*256;
        out[(size_t)m*DM+k] = (v[q]-mu)*rs*sc[k]+bi[k];
    }
}

// ---------------- generic NT GEMM: C[M,N] = A[M,K] @ B[N,K]^T ----------------
// EPI: 0 = plain, 1 = silu(acc + bias[n]), 2 = acc + res[m*ldc+n]
// A row address: m*lda + (m>>9)*padjump  (overlapping conv windows + batch pad jump)
#define GBM 128
#define GBN 64
#define GBK 16

template<int EPI>
__global__ __launch_bounds__(256)
void gemm_nt(const float* __restrict__ A, int lda, int padjump,
             const float* __restrict__ B, int ldb,
             float* __restrict__ C, int ldc,
             int K, const float* __restrict__ aux)
{
    __shared__ float As[2][GBK][GBM+4];
    __shared__ float Bs[2][GBK][GBN+4];
    const int tid = threadIdx.x;
    const int m0 = blockIdx.y * GBM;
    const int n0 = blockIdx.x * GBN;
    const int tx = tid & 15;
    const int ty = tid >> 4;

    const int akq = (tid & 3) * 4;
    const int ar  = tid >> 2;            // 0..63, second slot ar+64
    const int gmA0 = m0 + ar;
    const int gmA1 = m0 + ar + 64;
    const size_t aoff0 = (size_t)gmA0*lda + (size_t)(gmA0>>9)*padjump + akq;
    const size_t aoff1 = (size_t)gmA1*lda + (size_t)(gmA1>>9)*padjump + akq;
    const size_t boff  = (size_t)(n0+ar)*ldb + akq;

    float acc[8][4];
#pragma unroll
    for (int i=0;i<8;i++)
#pragma unroll
        for (int j=0;j<4;j++) acc[i][j]=0.f;

    { // prologue tile 0
        float4 a0 = *(const float4*)(A + aoff0);
        float4 a1 = *(const float4*)(A + aoff1);
        float4 b0 = *(const float4*)(B + boff);
        As[0][akq+0][ar]=a0.x; As[0][akq+1][ar]=a0.y; As[0][akq+2][ar]=a0.z; As[0][akq+3][ar]=a0.w;
        As[0][akq+0][ar+64]=a1.x; As[0][akq+1][ar+64]=a1.y; As[0][akq+2][ar+64]=a1.z; As[0][akq+3][ar+64]=a1.w;
        Bs[0][akq+0][ar]=b0.x; Bs[0][akq+1][ar]=b0.y; Bs[0][akq+2][ar]=b0.z; Bs[0][akq+3][ar]=b0.w;
    }
    __syncthreads();
    int cur = 0;
    const int KT = K / GBK;
    for (int kt=0; kt<KT; kt++){
        float4 nA0, nA1, nB0;
        if (kt+1 < KT){
            size_t ko = (size_t)(kt+1)*GBK;
            nA0 = *(const float4*)(A + aoff0 + ko);
            nA1 = *(const float4*)(A + aoff1 + ko);
            nB0 = *(const float4*)(B + boff + ko);
        }
#pragma unroll
        for (int k=0;k<GBK;k++){
            float4 av0 = *(const float4*)&As[cur][k][ty*8];
            float4 av1 = *(const float4*)&As[cur][k][ty*8+4];
            float4 bv  = *(const float4*)&Bs[cur][k][tx*4];
            float a[8] = {av0.x,av0.y,av0.z,av0.w,av1.x,av1.y,av1.z,av1.w};
            float bb[4]= {bv.x,bv.y,bv.z,bv.w};
#pragma unroll
            for (int i=0;i<8;i++)
#pragma unroll
                for (int j=0;j<4;j++) acc[i][j] += a[i]*bb[j];
        }
        if (kt+1 < KT){
            int nxt = cur^1;
            As[nxt][akq+0][ar]=nA0.x; As[nxt][akq+1][ar]=nA0.y; As[nxt][akq+2][ar]=nA0.z; As[nxt][akq+3][ar]=nA0.w;
            As[nxt][akq+0][ar+64]=nA1.x; As[nxt][akq+1][ar+64]=nA1.y; As[nxt][akq+2][ar+64]=nA1.z; As[nxt][akq+3][ar+64]=nA1.w;
            Bs[nxt][akq+0][ar]=nB0.x; Bs[nxt][akq+1][ar]=nB0.y; Bs[nxt][akq+2][ar]=nB0.z; Bs[nxt][akq+3][ar]=nB0.w;
            __syncthreads();
            cur = nxt;
        }
    }
#pragma unroll
    for (int i=0;i<8;i++){
        int gm = m0 + ty*8 + i;
        int gn = n0 + tx*4;
        float4 v = make_float4(acc[i][0],acc[i][1],acc[i][2],acc[i][3]);
        if (EPI==1){
            v.x = siluf(v.x + aux[gn+0]);
            v.y = siluf(v.y + aux[gn+1]);
            v.z = siluf(v.z + aux[gn+2]);
            v.w = siluf(v.w + aux[gn+3]);
        } else if (EPI==2){
            const float4 r = *(const float4*)(aux + (size_t)gm*ldc + gn);
            v.x+=r.x; v.y+=r.y; v.z+=r.z; v.w+=r.w;
        }
        *(float4*)(C + (size_t)gm*ldc + gn) = v;
    }
}

// ---------------- conv weight re-layout: wc[o][tau*DI+i] = conv_w[o][i][tau] ----------------
__global__ void wct_kernel(const float* __restrict__ cw, float* __restrict__ wc)
{
    int idx = blockIdx.x*blockDim.x + threadIdx.x;
    if (idx >= DI*KW) return;
    int o = idx / KW;
    int k = idx - o*KW;
    int tau = k / DI;
    int i = k - tau*DI;
    wc[idx] = cw[((size_t)o*DI + i)*KCONV + tau];
}

// ---------------- pad x_proj with 3 leading zero rows per batch ----------------
__global__ void pad_kernel(const float* __restrict__ xz, float* __restrict__ xpad)
{
    int idx = blockIdx.x*blockDim.x + threadIdx.x;
    if (idx >= BATCH*(TT+3)*DI) return;
    int i = idx % DI;
    int rb = idx / DI;
    int r = rb % (TT+3);
    int b = rb / (TT+3);
    float v = 0.f;
    if (r >= 3) v = xz[((size_t)(b*TT + (r-3)))*2*DI + i];
    xpad[idx] = v;
}

// ---------------- x_ssm = x_act @ W_x^T  (N=33) ----------------
__global__ void xssm_kernel(const float* __restrict__ xact,
                            const float* __restrict__ Wx,
                            float* __restrict__ out)
{
    int m = blockIdx.x;
    const float* xr = xact + (size_t)m*DI;
    float accv[33];
#pragma unroll
    for (int n=0;n<33;n++) accv[n]=0.f;
    for (int k = threadIdx.x; k < DI; k += 256){
        float xv = xr[k];
#pragma unroll
        for (int n=0;n<33;n++) accv[n] += xv * Wx[n*DI + k];
    }
    int lane=threadIdx.x&31, w=threadIdx.x>>5;
#pragma unroll
    for (int n=0;n<33;n++)
#pragma unroll
        for (int o=16;o;o>>=1) accv[n] += __shfl_down_sync(~0u, accv[n], o);
    __shared__ float sred[8][33];
    if (lane==0)
#pragma unroll
        for (int n=0;n<33;n++) sred[w][n]=accv[n];
    __syncthreads();
    if (threadIdx.x < 33){
        float s=0.f;
#pragma unroll
        for (int q=0;q<8;q++) s += sred[q][threadIdx.x];
        out[(size_t)m*33 + threadIdx.x] = s;
    }
}

// ---------------- decay = exp(-softplus(d_raw*Wdt + bdt)) = sigmoid(-a) ----------------
__global__ void decay_kernel(const float* __restrict__ xssm,
                             const float* __restrict__ Wdt,
                             const float* __restrict__ bdt,
                             float* __restrict__ decay)
{
    int i = blockIdx.x*blockDim.x + threadIdx.x;
    if (i >= NROW*DI) return;
    int d = i % DI;
    int row = i / DI;
    float a = xssm[(size_t)row*33] * Wdt[d] + bdt[d];
    decay[i] = 1.0f/(1.0f + expf(a));
}

// ---------------- adjacency preprocess: ordered nonzero lists (strict lower tri) ----------------
__global__ void adj_kernel(const int* __restrict__ adj,
                           int* __restrict__ nzlist,
                           int* __restrict__ nnz,
                           float* __restrict__ invdeg)
{
    int rowid = blockIdx.x;          // b*TT + t
    int t = rowid & (TT-1);
    int lane = threadIdx.x;
    const int* arow = adj + (size_t)rowid*TT;
    int* outrow = nzlist + (size_t)rowid*TT;
    int cnt = 0;
    for (int s0 = 0; s0 < t; s0 += 32){
        int s = s0 + lane;
        bool nz = (s < t) && (arow[s] != 0);
        unsigned m = __ballot_sync(~0u, nz);
        if (nz){
            int pos = cnt + __popc(m & ((1u<<lane)-1u));
            outrow[pos] = s;
        }
        cnt += __popc(m);
    }
    if (lane==0){
        nnz[rowid] = cnt;
        invdeg[rowid] = 1.0f / (float)(cnt < 1 ? 1 : cnt);
    }
}

// ---------------- the scan: one thread per (channel d, state n); no grid sync needed ----------------
__global__ __launch_bounds__(512)
void scan_kernel(const float* __restrict__ decay, const float* __restrict__ xact,
                 const float* __restrict__ xssm,  const float* __restrict__ xz,
                 const int* __restrict__ nzlist,  const int* __restrict__ nnz_arr,
                 const float* __restrict__ invdeg,
                 const float* __restrict__ Wg,    const float* __restrict__ bg,
                 float* __restrict__ hist,        float* __restrict__ G)
{
    const int NB = DI/32;            // 48 blocks per batch
    int b = blockIdx.x / NB;
    int dblk = blockIdx.x - b*NB;
    int tid = threadIdx.x;
    int dl = tid & 31;
    int n  = tid >> 5;               // 0..15
    int d  = dblk*32 + dl;

    __shared__ float sWg[16][16];
    __shared__ float sG[16][32];
    __shared__ float sY[16][32];
    if (tid < 256) sWg[tid>>4][tid&15] = Wg[tid];
    float bgn = bg[n];
    __syncthreads();

    float h = 0.f;
    float* histb = hist + ((size_t)b*TT*DS + n)*DI + d;   // + s*DS*DI

    for (int t=0; t<TT; t++){
        int row = b*TT + t;
        float dec = decay[(size_t)row*DI + d];
        float xa  = xact [(size_t)row*DI + d];
        float Bn  = xssm[(size_t)row*33 + 1 + n];
        float Cn  = xssm[(size_t)row*33 + 17 + n];
        h = h*dec + Bn*xa;

        int nz = nnz_arr[row];
        const int* nzp = nzlist + (size_t)row*TT;
        float g = 0.f;
        int j = 0;
        for (; j+4 <= nz; j += 4){
            int s0=nzp[j], s1=nzp[j+1], s2=nzp[j+2], s3=nzp[j+3];
            g += histb[(size_t)s0*(DS*DI)] + histb[(size_t)s1*(DS*DI)]
               + histb[(size_t)s2*(DS*DI)] + histb[(size_t)s3*(DS*DI)];
        }
        for (; j < nz; j++) g += histb[(size_t)nzp[j]*(DS*DI)];
        g *= invdeg[row];

        sG[n][dl] = g;
        __syncthreads();                      // S1
        float acc = bgn;
#pragma unroll
        for (int m=0;m<16;m++) acc += sG[m][dl]*sWg[n][m];
        float upd = 0.1f * acc / (1.f + __expf(-acc));
        int nzAll = nnz_arr[t] + nnz_arr[TT + t];   // global 'any' across both batches
        if (nzAll > 0) h += upd;

        histb[(size_t)t*(DS*DI)] = h;
        sY[n][dl] = h * Cn;
        __syncthreads();                      // S2
        if (n == 0){
            float y = 0.f;
#pragma unroll
            for (int m=0;m<16;m++) y += sY[m][dl];
            float zz = xz[(size_t)row*2*DI + DI + d];
            G[(size_t)row*DI + d] = y * (zz / (1.f + __expf(-zz)));
        }
    }
}

// ---------------- launch ----------------
extern "C" void kernel_launch(void* const* d_in, const int* in_sizes, int n_in,
                              void* d_out, int out_size)
{
    (void)in_sizes; (void)n_in; (void)out_size;
    const float* x        = (const float*)d_in[0];
    const int*   adj      = (const int*)  d_in[1];
    const float* ln_scale = (const float*)d_in[2];
    const float* ln_bias  = (const float*)d_in[3];
    const float* W_in     = (const float*)d_in[4];
    const float* conv_w   = (const float*)d_in[5];
    const float* conv_b   = (const float*)d_in[6];
    const float* W_x      = (const float*)d_in[7];
    const float* W_dt     = (const float*)d_in[8];
    const float* b_dt     = (const float*)d_in[9];
    const float* W_g      = (const float*)d_in[10];
    const float* b_g      = (const float*)d_in[11];
    const float* W_out    = (const float*)d_in[12];
    float* out = (float*)d_out;

    float *p_xn, *p_xz, *p_xpad, *p_xact, *p_wc, *p_xssm, *p_decay, *p_hist, *p_G, *p_invdeg;
    int *p_nz, *p_nnz;
    cudaGetSymbolAddress((void**)&p_xn,    g_xn);
    cudaGetSymbolAddress((void**)&p_xz,    g_xz);
    cudaGetSymbolAddress((void**)&p_xpad,  g_xpad);
    cudaGetSymbolAddress((void**)&p_xact,  g_xact);
    cudaGetSymbolAddress((void**)&p_wc,    g_wc);
    cudaGetSymbolAddress((void**)&p_xssm,  g_xssm);
    cudaGetSymbolAddress((void**)&p_decay, g_decay);
    cudaGetSymbolAddress((void**)&p_hist,  g_hist);
    cudaGetSymbolAddress((void**)&p_G,     g_G);
    cudaGetSymbolAddress((void**)&p_nz,    g_nz);
    cudaGetSymbolAddress((void**)&p_nnz,   g_nnz);
    cudaGetSymbolAddress((void**)&p_invdeg,g_invdeg);

    // 1. layernorm
    ln_kernel<<<NROW, 256>>>(x, ln_scale, ln_bias, p_xn);
    // 2. xz = xn @ W_in^T   (M=1024, N=3072, K=768)
    gemm_nt<0><<<dim3(2*DI/GBN, NROW/GBM), 256>>>(p_xn, DM, 0, W_in, DM, p_xz, 2*DI, DM, nullptr);
    // 3. conv weight re-layout
    wct_kernel<<<(DI*KW + 255)/256, 256>>>(conv_w, p_wc);
    // 4. pad x_proj
    pad_kernel<<<(BATCH*(TT+3)*DI + 255)/256, 256>>>(p_xz, p_xpad);
    // 5. conv as GEMM (M=1024, N=1536, K=6144, overlapping windows) + bias + silu
    gemm_nt<1><<<dim3(DI/GBN, NROW/GBM), 256>>>(p_xpad, DI, 3*DI, p_wc, KW, p_xact, DI, KW, conv_b);
    // 6. x_ssm
    xssm_kernel<<<NROW, 256>>>(p_xact, W_x, p_xssm);
    // 7. decay
    decay_kernel<<<(NROW*DI + 255)/256, 256>>>(p_xssm, W_dt, b_dt, p_decay);
    // 8. adjacency nonzero lists
    adj_kernel<<<NROW, 32>>>(adj, p_nz, p_nnz, p_invdeg);
    // 9. scan (writes G = y * silu(z))
    scan_kernel<<<BATCH*(DI/32), 512>>>(p_decay, p_xact, p_xssm, p_xz,
                                        p_nz, p_nnz, p_invdeg, W_g, b_g, p_hist, p_G);
    // 10. out = G @ W_out^T + x   (M=1024, N=768, K=1536)
    gemm_nt<2><<<dim3(DM/GBN, NROW/GBM), 256>>>(p_G, DI, 0, W_out, DI, out, DM, DI, x);
}

// round 2
// speedup vs baseline: 3.0656x; 3.0656x over previous
#include <cuda_runtime.h>
#include <cstdint>

#define BATCH 2
#define TT 512
#define DM 768
#define DI 1536
#define DS 16
#define NROW (BATCH*TT)          // 1024
#define KCONV 4
#define KW (KCONV*DI)            // 6144
#define ND (DS*DI)               // 24576  (n,d) feature width
#define CH 64                    // time chunk
#define NCHUNK (TT/CH)           // 8

// ---------------- scratch (device globals; no allocation allowed) ----------------
__device__ __align__(16) float g_xn   [NROW*DM];
__device__ __align__(16) float g_xz   [NROW*2*DI];
__device__ __align__(16) float g_xpad [BATCH*(TT+3)*DI];
__device__ __align__(16) float g_xact [NROW*DI];
__device__ __align__(16) float g_wc   [DI*KW];
__device__ __align__(16) float g_xssm [NROW*33];
__device__ __align__(16) float g_decay[NROW*DI];
__device__ __align__(16) float g_hist [(size_t)BATCH*TT*ND];      // [b][s][n][d]
__device__ __align__(16) float g_G    [NROW*DI];
__device__ __align__(16) float g_gpast[(size_t)BATCH*CH*ND];      // per-chunk cross-chunk gather
__device__ __align__(16) float g_hcarry[BATCH*ND];
__device__ __align__(16) unsigned g_wmask[NROW*16];               // row-major adjacency bits (strict lower)
__device__ __align__(16) uint2 g_cm[BATCH*NCHUNK*TT];             // transposed: bit j = w[t0+j][s]
__device__ int   g_nnz[NROW];
__device__ float g_invdeg[NROW];

__device__ __forceinline__ float siluf(float v){ return v / (1.f + __expf(-v)); }

// ---------------- layernorm ----------------
__global__ void ln_kernel(const float* __restrict__ x,
                          const float* __restrict__ sc,
                          const float* __restrict__ bi,
                          float* __restrict__ out)
{
    int m = blockIdx.x;
    const float* xr = x + (size_t)m*DM;
    int tid = threadIdx.x;
    float v[3]; float s=0.f, sq=0.f;
#pragma unroll
    for (int q=0;q<3;q++){ v[q]=xr[tid+q*256]; s+=v[q]; sq+=v[q]*v[q]; }
#pragma unroll
    for (int o=16;o;o>>=1){ s+=__shfl_down_sync(~0u,s,o); sq+=__shfl_down_sync(~0u,sq,o); }
    __shared__ float sh0[8], sh1[8];
    int lane=tid&31, w=tid>>5;
    if (lane==0){ sh0[w]=s; sh1[w]=sq; }
    __syncthreads();
    __shared__ float smu, srs;
    if (tid==0){
        float S=0.f,SQ=0.f;
#pragma unroll
        for (int i=0;i<8;i++){ S+=sh0[i]; SQ+=sh1[i]; }
        float mu=S/(float)DM;
        float var=SQ/(float)DM - mu*mu;
        smu=mu; srs=rsqrtf(var+1e-5f);
    }
    __syncthreads();
    float mu=smu, rs=srs;
#pragma unroll
    for (int q=0;q<3;q++){
        int k=tid+q*256;
        out[(size_t)m*DM+k] = (v[q]-mu)*rs*sc[k]+bi[k];
    }
}

// ---------------- generic NT GEMM: C[M,N] = A[M,K] @ B[N,K]^T ----------------
#define GBM 128
#define GBN 64
#define GBK 16

template<int EPI>
__global__ __launch_bounds__(256)
void gemm_nt(const float* __restrict__ A, int lda, int padjump,
             const float* __restrict__ B, int ldb,
             float* __restrict__ C, int ldc,
             int K, const float* __restrict__ aux)
{
    __shared__ float As[2][GBK][GBM+4];
    __shared__ float Bs[2][GBK][GBN+4];
    const int tid = threadIdx.x;
    const int m0 = blockIdx.y * GBM;
    const int n0 = blockIdx.x * GBN;
    const int tx = tid & 15;
    const int ty = tid >> 4;

    const int akq = (tid & 3) * 4;
    const int ar  = tid >> 2;
    const int gmA0 = m0 + ar;
    const int gmA1 = m0 + ar + 64;
    const size_t aoff0 = (size_t)gmA0*lda + (size_t)(gmA0>>9)*padjump + akq;
    const size_t aoff1 = (size_t)gmA1*lda + (size_t)(gmA1>>9)*padjump + akq;
    const size_t boff  = (size_t)(n0+ar)*ldb + akq;

    float acc[8][4];
#pragma unroll
    for (int i=0;i<8;i++)
#pragma unroll
        for (int j=0;j<4;j++) acc[i][j]=0.f;

    {
        float4 a0 = *(const float4*)(A + aoff0);
        float4 a1 = *(const float4*)(A + aoff1);
        float4 b0 = *(const float4*)(B + boff);
        As[0][akq+0][ar]=a0.x; As[0][akq+1][ar]=a0.y; As[0][akq+2][ar]=a0.z; As[0][akq+3][ar]=a0.w;
        As[0][akq+0][ar+64]=a1.x; As[0][akq+1][ar+64]=a1.y; As[0][akq+2][ar+64]=a1.z; As[0][akq+3][ar+64]=a1.w;
        Bs[0][akq+0][ar]=b0.x; Bs[0][akq+1][ar]=b0.y; Bs[0][akq+2][ar]=b0.z; Bs[0][akq+3][ar]=b0.w;
    }
    __syncthreads();
    int cur = 0;
    const int KT = K / GBK;
    for (int kt=0; kt<KT; kt++){
        float4 nA0, nA1, nB0;
        if (kt+1 < KT){
            size_t ko = (size_t)(kt+1)*GBK;
            nA0 = *(const float4*)(A + aoff0 + ko);
            nA1 = *(const float4*)(A + aoff1 + ko);
            nB0 = *(const float4*)(B + boff + ko);
        }
#pragma unroll
        for (int k=0;k<GBK;k++){
            float4 av0 = *(const float4*)&As[cur][k][ty*8];
            float4 av1 = *(const float4*)&As[cur][k][ty*8+4];
            float4 bv  = *(const float4*)&Bs[cur][k][tx*4];
            float a[8] = {av0.x,av0.y,av0.z,av0.w,av1.x,av1.y,av1.z,av1.w};
            float bb[4]= {bv.x,bv.y,bv.z,bv.w};
#pragma unroll
            for (int i=0;i<8;i++)
#pragma unroll
                for (int j=0;j<4;j++) acc[i][j] += a[i]*bb[j];
        }
        if (kt+1 < KT){
            int nxt = cur^1;
            As[nxt][akq+0][ar]=nA0.x; As[nxt][akq+1][ar]=nA0.y; As[nxt][akq+2][ar]=nA0.z; As[nxt][akq+3][ar]=nA0.w;
            As[nxt][akq+0][ar+64]=nA1.x; As[nxt][akq+1][ar+64]=nA1.y; As[nxt][akq+2][ar+64]=nA1.z; As[nxt][akq+3][ar+64]=nA1.w;
            Bs[nxt][akq+0][ar]=nB0.x; Bs[nxt][akq+1][ar]=nB0.y; Bs[nxt][akq+2][ar]=nB0.z; Bs[nxt][akq+3][ar]=nB0.w;
            __syncthreads();
            cur = nxt;
        }
    }
#pragma unroll
    for (int i=0;i<8;i++){
        int gm = m0 + ty*8 + i;
        int gn = n0 + tx*4;
        float4 v = make_float4(acc[i][0],acc[i][1],acc[i][2],acc[i][3]);
        if (EPI==1){
            v.x = siluf(v.x + aux[gn+0]);
            v.y = siluf(v.y + aux[gn+1]);
            v.z = siluf(v.z + aux[gn+2]);
            v.w = siluf(v.w + aux[gn+3]);
        } else if (EPI==2){
            const float4 r = *(const float4*)(aux + (size_t)gm*ldc + gn);
            v.x+=r.x; v.y+=r.y; v.z+=r.z; v.w+=r.w;
        }
        *(float4*)(C + (size_t)gm*ldc + gn) = v;
    }
}

// ---------------- conv weight re-layout ----------------
__global__ void wct_kernel(const float* __restrict__ cw, float* __restrict__ wc)
{
    int idx = blockIdx.x*blockDim.x + threadIdx.x;
    if (idx >= DI*KW) return;
    int o = idx / KW;
    int k = idx - o*KW;
    int tau = k / DI;
    int i = k - tau*DI;
    wc[idx] = cw[((size_t)o*DI + i)*KCONV + tau];
}

// ---------------- pad x_proj with 3 leading zero rows per batch ----------------
__global__ void pad_kernel(const float* __restrict__ xz, float* __restrict__ xpad)
{
    int idx = blockIdx.x*blockDim.x + threadIdx.x;
    if (idx >= BATCH*(TT+3)*DI) return;
    int i = idx % DI;
    int rb = idx / DI;
    int r = rb % (TT+3);
    int b = rb / (TT+3);
    float v = 0.f;
    if (r >= 3) v = xz[((size_t)(b*TT + (r-3)))*2*DI + i];
    xpad[idx] = v;
}

// ---------------- x_ssm = x_act @ W_x^T  (N=33) ----------------
__global__ void xssm_kernel(const float* __restrict__ xact,
                            const float* __restrict__ Wx,
                            float* __restrict__ out)
{
    int m = blockIdx.x;
    const float* xr = xact + (size_t)m*DI;
    float accv[33];
#pragma unroll
    for (int n=0;n<33;n++) accv[n]=0.f;
    for (int k = threadIdx.x; k < DI; k += 256){
        float xv = xr[k];
#pragma unroll
        for (int n=0;n<33;n++) accv[n] += xv * Wx[n*DI + k];
    }
    int lane=threadIdx.x&31, w=threadIdx.x>>5;
#pragma unroll
    for (int n=0;n<33;n++)
#pragma unroll
        for (int o=16;o;o>>=1) accv[n] += __shfl_down_sync(~0u, accv[n], o);
    __shared__ float sred[8][33];
    if (lane==0)
#pragma unroll
        for (int n=0;n<33;n++) sred[w][n]=accv[n];
    __syncthreads();
    if (threadIdx.x < 33){
        float s=0.f;
#pragma unroll
        for (int q=0;q<8;q++) s += sred[q][threadIdx.x];
        out[(size_t)m*33 + threadIdx.x] = s;
    }
}

// ---------------- decay = sigmoid(-(d_raw*Wdt + bdt)) ----------------
__global__ void decay_kernel(const float* __restrict__ xssm,
                             const float* __restrict__ Wdt,
                             const float* __restrict__ bdt,
                             float* __restrict__ decay)
{
    int i = blockIdx.x*blockDim.x + threadIdx.x;
    if (i >= NROW*DI) return;
    int d = i % DI;
    int row = i / DI;
    float a = xssm[(size_t)row*33] * Wdt[d] + bdt[d];
    decay[i] = 1.0f/(1.0f + expf(a));
}

// ---------------- adjacency -> row bitmasks + nnz + invdeg ----------------
__global__ void adj_kernel(const int* __restrict__ adj,
                           unsigned* __restrict__ wmask,
                           int* __restrict__ nnz,
                           float* __restrict__ invdeg)
{
    int rowid = blockIdx.x;          // b*TT + t
    int t = rowid & (TT-1);
    int lane = threadIdx.x;
    const int* arow = adj + (size_t)rowid*TT;
    int cnt = 0;
    for (int w = 0; w < 16; w++){
        int s = w*32 + lane;
        bool nz = (s < t) && (arow[s] != 0);
        unsigned m = __ballot_sync(~0u, nz);
        if (lane==0) wmask[rowid*16 + w] = m;
        cnt += __popc(m);
    }
    if (lane==0){
        nnz[rowid] = cnt;
        invdeg[rowid] = 1.0f / (float)(cnt < 1 ? 1 : cnt);
    }
}

// ---------------- transposed chunk masks: cm[b][k][s].x bit j = w[t0+j][s], .y bit j = w[t0+32+j][s] ----------------
__global__ void cmt_kernel(const int* __restrict__ adj, uint2* __restrict__ cm)
{
    int s = threadIdx.x;             // 0..511
    int k = blockIdx.x;              // chunk
    int b = blockIdx.y;
    int t0 = k*CH;
    unsigned m0=0, m1=0;
#pragma unroll
    for (int j=0;j<32;j++){
        int t = t0 + j;
        if (s < t && adj[((size_t)(b*TT+t))*TT + s] != 0) m0 |= 1u<<j;
    }
#pragma unroll
    for (int j=0;j<32;j++){
        int t = t0 + 32 + j;
        if (s < t && adj[((size_t)(b*TT+t))*TT + s] != 0) m1 |= 1u<<j;
    }
    cm[((size_t)b*NCHUNK + k)*TT + s] = make_uint2(m0,m1);
}

// ---------------- cross-chunk masked sum: Gpast[b][j][e] = sum_{s<t0, w[t0+j][s]} hist[b][s][e] ----------------
__global__ __launch_bounds__(256)
void gpast_kernel(const float* __restrict__ hist,
                  const uint2* __restrict__ cm,
                  float* __restrict__ Gpast, int k)
{
    int b = blockIdx.y;
    int e = blockIdx.x*256 + threadIdx.x;   // grid.x = ND/256 = 96
    int t0 = k*CH;
    const uint2* cmb = cm + ((size_t)b*NCHUNK + k)*TT;
    const float* hb = hist + (size_t)b*TT*ND + e;
    float acc[CH];
#pragma unroll
    for (int j=0;j<CH;j++) acc[j]=0.f;
#pragma unroll 2
    for (int s=0;s<t0;s++){
        float val = hb[(size_t)s*ND];
        uint2 m = cmb[s];                    // uniform (broadcast) load
#pragma unroll
        for (int j=0;j<32;j++) if (m.x & (1u<<j)) acc[j] += val;
#pragma unroll
        for (int j=0;j<32;j++) if (m.y & (1u<<j)) acc[j+32] += val;
    }
    float* gp = Gpast + (size_t)b*CH*ND + e;
#pragma unroll
    for (int j=0;j<CH;j++) gp[(size_t)j*ND] = acc[j];
}

// ---------------- sequential scan over one chunk; chunk hist in SMEM ----------------
__global__ __launch_bounds__(512)
void scan_chunk(const float* __restrict__ decay, const float* __restrict__ xact,
                const float* __restrict__ xssm,  const float* __restrict__ xz,
                const unsigned* __restrict__ wmask, const int* __restrict__ nnz_arr,
                const float* __restrict__ invdeg,
                const float* __restrict__ Wg,    const float* __restrict__ bg,
                const float* __restrict__ Gpast,
                float* __restrict__ hist,        float* __restrict__ G,
                float* __restrict__ hcarry,      int k)
{
    extern __shared__ float lh[];            // [CH][512]
    const int NB = DI/32;                    // 48
    int b = blockIdx.x / NB;
    int dblk = blockIdx.x - b*NB;
    int tid = threadIdx.x;
    int dl = tid & 31;
    int n  = tid >> 5;                       // 0..15
    int d  = dblk*32 + dl;
    int e  = n*DI + d;

    __shared__ float sWg[256];
    __shared__ float sG[512];
    __shared__ float sY[512];
    if (tid < 256) sWg[tid] = Wg[tid];
    float bgn = bg[n];

    float h = (k==0) ? 0.f : hcarry[(size_t)b*ND + e];
    __syncthreads();

    const int t0 = k*CH;
    for (int tt=0; tt<CH; tt++){
        int t = t0 + tt;
        int row = b*TT + t;
        float dec = decay[(size_t)row*DI + d];
        float xa  = xact [(size_t)row*DI + d];
        float Bn  = xssm[(size_t)row*33 + 1 + n];
        float Cn  = xssm[(size_t)row*33 + 17 + n];
        h = h*dec + Bn*xa;

        // gather: cross-chunk (precomputed) + within-chunk (smem, uniform bit-walk)
        float g = (k>0) ? Gpast[((size_t)b*CH + tt)*ND + e] : 0.f;
        unsigned m0 = wmask[row*16 + 2*k];
        unsigned m1 = wmask[row*16 + 2*k+1];
        while (m0){ int p=__ffs(m0)-1; m0 &= m0-1; g += lh[p*512 + tid]; }
        while (m1){ int p=__ffs(m1)-1; m1 &= m1-1; g += lh[(p+32)*512 + tid]; }
        g *= invdeg[row];

        sG[tid] = g;
        __syncthreads();                      // S1
        float a = bgn;
#pragma unroll
        for (int m=0;m<16;m++) a += sG[m*32 + dl]*sWg[n*16 + m];
        float upd = 0.1f * a / (1.f + expf(-a));
        if (nnz_arr[t] + nnz_arr[TT + t] > 0) h += upd;

        lh[tt*512 + tid] = h;                 // own column only; no barrier needed
        sY[tid] = h * Cn;
        __syncthreads();                      // S2
        if (n == 0){
            float y = 0.f;
#pragma unroll
            for (int m=0;m<16;m++) y += sY[m*32 + dl];
            float zz = xz[(size_t)row*2*DI + DI + d];
            G[(size_t)row*DI + d] = y * (zz / (1.f + __expf(-zz)));
        }
    }

    // flush chunk hist to global + carry h
    __syncthreads();
#pragma unroll 4
    for (int tt=0; tt<CH; tt++)
        hist[((size_t)(b*TT + t0 + tt))*ND + e] = lh[tt*512 + tid];
    hcarry[(size_t)b*ND + e] = h;
}

// ---------------- launch ----------------
extern "C" void kernel_launch(void* const* d_in, const int* in_sizes, int n_in,
                              void* d_out, int out_size)
{
    (void)in_sizes; (void)n_in; (void)out_size;
    const float* x        = (const float*)d_in[0];
    const int*   adj      = (const int*)  d_in[1];
    const float* ln_scale = (const float*)d_in[2];
    const float* ln_bias  = (const float*)d_in[3];
    const float* W_in     = (const float*)d_in[4];
    const float* conv_w   = (const float*)d_in[5];
    const float* conv_b   = (const float*)d_in[6];
    const float* W_x      = (const float*)d_in[7];
    const float* W_dt     = (const float*)d_in[8];
    const float* b_dt     = (const float*)d_in[9];
    const float* W_g      = (const float*)d_in[10];
    const float* b_g      = (const float*)d_in[11];
    const float* W_out    = (const float*)d_in[12];
    float* out = (float*)d_out;

    float *p_xn, *p_xz, *p_xpad, *p_xact, *p_wc, *p_xssm, *p_decay, *p_hist, *p_G,
          *p_invdeg, *p_gpast, *p_hcarry;
    unsigned *p_wmask; uint2 *p_cm; int *p_nnz;
    cudaGetSymbolAddress((void**)&p_xn,    g_xn);
    cudaGetSymbolAddress((void**)&p_xz,    g_xz);
    cudaGetSymbolAddress((void**)&p_xpad,  g_xpad);
    cudaGetSymbolAddress((void**)&p_xact,  g_xact);
    cudaGetSymbolAddress((void**)&p_wc,    g_wc);
    cudaGetSymbolAddress((void**)&p_xssm,  g_xssm);
    cudaGetSymbolAddress((void**)&p_decay, g_decay);
    cudaGetSymbolAddress((void**)&p_hist,  g_hist);
    cudaGetSymbolAddress((void**)&p_G,     g_G);
    cudaGetSymbolAddress((void**)&p_gpast, g_gpast);
    cudaGetSymbolAddress((void**)&p_hcarry,g_hcarry);
    cudaGetSymbolAddress((void**)&p_wmask, g_wmask);
    cudaGetSymbolAddress((void**)&p_cm,    g_cm);
    cudaGetSymbolAddress((void**)&p_nnz,   g_nnz);
    cudaGetSymbolAddress((void**)&p_invdeg,g_invdeg);

    cudaFuncSetAttribute(scan_chunk, cudaFuncAttributeMaxDynamicSharedMemorySize,
                         CH*512*sizeof(float));

    // 1. layernorm
    ln_kernel<<<NROW, 256>>>(x, ln_scale, ln_bias, p_xn);
    // 2. xz = xn @ W_in^T
    gemm_nt<0><<<dim3(2*DI/GBN, NROW/GBM), 256>>>(p_xn, DM, 0, W_in, DM, p_xz, 2*DI, DM, nullptr);
    // 3. conv weight re-layout
    wct_kernel<<<(DI*KW + 255)/256, 256>>>(conv_w, p_wc);
    // 4. pad x_proj
    pad_kernel<<<(BATCH*(TT+3)*DI + 255)/256, 256>>>(p_xz, p_xpad);
    // 5. conv as GEMM + bias + silu
    gemm_nt<1><<<dim3(DI/GBN, NROW/GBM), 256>>>(p_xpad, DI, 3*DI, p_wc, KW, p_xact, DI, KW, conv_b);
    // 6. x_ssm
    xssm_kernel<<<NROW, 256>>>(p_xact, W_x, p_xssm);
    // 7. decay
    decay_kernel<<<(NROW*DI + 255)/256, 256>>>(p_xssm, W_dt, b_dt, p_decay);
    // 8. adjacency bitmasks
    adj_kernel<<<NROW, 32>>>(adj, p_wmask, p_nnz, p_invdeg);
    // 9. transposed chunk masks
    cmt_kernel<<<dim3(NCHUNK, BATCH), TT>>>(adj, p_cm);
    // 10. chunked scan
    for (int k = 0; k < NCHUNK; k++){
        if (k > 0)
            gpast_kernel<<<dim3(ND/256, BATCH), 256>>>(p_hist, p_cm, p_gpast, k);
        scan_chunk<<<BATCH*(DI/32), 512, CH*512*sizeof(float)>>>(
            p_decay, p_xact, p_xssm, p_xz, p_wmask, p_nnz, p_invdeg,
            W_g, b_g, p_gpast, p_hist, p_G, p_hcarry, k);
    }
    // 11. out = G @ W_out^T + x
    gemm_nt<2><<<dim3(DM/GBN, NROW/GBM), 256>>>(p_G, DI, 0, W_out, DI, out, DM, DI, x);
}